// round 4
// baseline (speedup 1.0000x reference)
#include <cuda_runtime.h>
#include <math.h>

// Problem constants
#define Bq   4
#define TTq  4096
#define Cq   1024
#define Hq   16
#define Kq   64
#define Tq   128
#define Nq   (TTq / Tq)      // 32 chunks
#define BT   (Bq * TTq)      // 16384 rows

// ---------------- scratch (static device arrays; no allocation) -------------
__device__ float g_xr[BT * Cq];   // mix_r input; later reused as attention output xo
__device__ float g_xk[BT * Cq];   // mix_k input; later reused as gated/normed y
__device__ float g_xv[BT * Cq];
__device__ float g_xg[BT * Cq];
__device__ float g_r [BT * Cq];
__device__ float g_k [BT * Cq];
__device__ float g_v [BT * Cq];
__device__ float g_g [BT * Cq];
__device__ float g_A [Nq * Bq * Hq * Kq * Kq];   // per-chunk k^T w v
__device__ float g_S [Nq * Bq * Hq * Kq * Kq];   // state before each chunk

// ---------------- helpers ---------------------------------------------------
union F4U { float4 f; unsigned long long u[2]; };

__device__ __forceinline__ unsigned long long ffma2(unsigned long long a,
                                                    unsigned long long b,
                                                    unsigned long long c) {
    unsigned long long d;
    asm("fma.rn.f32x2 %0, %1, %2, %3;" : "=l"(d) : "l"(a), "l"(b), "l"(c));
    return d;
}
__device__ __forceinline__ float lo32(unsigned long long v) {
    return __uint_as_float((unsigned)(v & 0xffffffffu));
}
__device__ __forceinline__ float hi32(unsigned long long v) {
    return __uint_as_float((unsigned)(v >> 32));
}

// ---------------- 1) time-shift mixing --------------------------------------
__global__ __launch_bounds__(256)
void mix_kernel(const float* __restrict__ x,
                const float* __restrict__ tmr, const float* __restrict__ tmk,
                const float* __restrict__ tmv, const float* __restrict__ tmg)
{
    int idx = blockIdx.x * 256 + threadIdx.x;   // float4 index, grid exact
    int e = idx * 4;
    int c = e & (Cq - 1);
    int bt = e >> 10;
    int t = bt & (TTq - 1);

    float4 xc = *(const float4*)(x + e);
    float4 xp = make_float4(0.f, 0.f, 0.f, 0.f);
    if (t != 0) xp = *(const float4*)(x + e - Cq);

    float4 mr = *(const float4*)(tmr + c);
    float4 mk = *(const float4*)(tmk + c);
    float4 mv = *(const float4*)(tmv + c);
    float4 mg = *(const float4*)(tmg + c);

    float4 o;
    o.x = xc.x * mr.x + xp.x * (1.f - mr.x);
    o.y = xc.y * mr.y + xp.y * (1.f - mr.y);
    o.z = xc.z * mr.z + xp.z * (1.f - mr.z);
    o.w = xc.w * mr.w + xp.w * (1.f - mr.w);
    *(float4*)(g_xr + e) = o;
    o.x = xc.x * mk.x + xp.x * (1.f - mk.x);
    o.y = xc.y * mk.y + xp.y * (1.f - mk.y);
    o.z = xc.z * mk.z + xp.z * (1.f - mk.z);
    o.w = xc.w * mk.w + xp.w * (1.f - mk.w);
    *(float4*)(g_xk + e) = o;
    o.x = xc.x * mv.x + xp.x * (1.f - mv.x);
    o.y = xc.y * mv.y + xp.y * (1.f - mv.y);
    o.z = xc.z * mv.z + xp.z * (1.f - mv.z);
    o.w = xc.w * mv.w + xp.w * (1.f - mv.w);
    *(float4*)(g_xv + e) = o;
    o.x = xc.x * mg.x + xp.x * (1.f - mg.x);
    o.y = xc.y * mg.y + xp.y * (1.f - mg.y);
    o.z = xc.z * mg.z + xp.z * (1.f - mg.z);
    o.w = xc.w * mg.w + xp.w * (1.f - mg.w);
    *(float4*)(g_xg + e) = o;
}

// ---------------- 2) GEMM: C[m,n] = sum_k A[m,k] * W[n,k] -------------------
// fp32 via packed f32x2 FMA. 128x128x16 tile, 256 threads, 8x8 per thread.
// A smem tile stored DUPLICATED (each value twice) so the broadcast operand is
// already in dup-pair form; B pairs are natural from contiguous smem.
#define GBM 128
#define GBN 128
#define GBK 16

__global__ __launch_bounds__(256, 2)
void gemm_nt(const float* __restrict__ A, const float* __restrict__ W,
             float* __restrict__ Cmat, int M, int N, int Kd)
{
    __shared__ float Asd[GBK][264];   // duplicated A tile (256 used + pad)
    __shared__ float Wsm[GBK][132];   // W tile (128 used + pad)

    int t  = threadIdx.x;
    int bm = blockIdx.y, bn = blockIdx.x;
    const float* Ap = A + (size_t)bm * GBM * Kd;
    const float* Wp = W + (size_t)bn * GBN * Kd;

    int lrow = t >> 2;          // 0..63
    int lk4  = (t & 3) * 4;     // 0,4,8,12
    int tr   = t >> 4;          // 0..15
    int tc   = t & 15;          // 0..15

    unsigned long long acc[8][4];
#pragma unroll
    for (int i = 0; i < 8; i++)
#pragma unroll
        for (int j = 0; j < 4; j++) acc[i][j] = 0ull;

    for (int k0 = 0; k0 < Kd; k0 += GBK) {
        float4 a0 = *(const float4*)(Ap + (size_t)lrow        * Kd + k0 + lk4);
        float4 a1 = *(const float4*)(Ap + (size_t)(lrow + 64) * Kd + k0 + lk4);
        float4 w0 = *(const float4*)(Wp + (size_t)lrow        * Kd + k0 + lk4);
        float4 w1 = *(const float4*)(Wp + (size_t)(lrow + 64) * Kd + k0 + lk4);
        __syncthreads();
        int r2a = 2 * lrow, r2b = 2 * (lrow + 64);
        Asd[lk4 + 0][r2a] = a0.x; Asd[lk4 + 0][r2a + 1] = a0.x;
        Asd[lk4 + 1][r2a] = a0.y; Asd[lk4 + 1][r2a + 1] = a0.y;
        Asd[lk4 + 2][r2a] = a0.z; Asd[lk4 + 2][r2a + 1] = a0.z;
        Asd[lk4 + 3][r2a] = a0.w; Asd[lk4 + 3][r2a + 1] = a0.w;
        Asd[lk4 + 0][r2b] = a1.x; Asd[lk4 + 0][r2b + 1] = a1.x;
        Asd[lk4 + 1][r2b] = a1.y; Asd[lk4 + 1][r2b + 1] = a1.y;
        Asd[lk4 + 2][r2b] = a1.z; Asd[lk4 + 2][r2b + 1] = a1.z;
        Asd[lk4 + 3][r2b] = a1.w; Asd[lk4 + 3][r2b + 1] = a1.w;
        Wsm[lk4 + 0][lrow] = w0.x; Wsm[lk4 + 0][lrow + 64] = w1.x;
        Wsm[lk4 + 1][lrow] = w0.y; Wsm[lk4 + 1][lrow + 64] = w1.y;
        Wsm[lk4 + 2][lrow] = w0.z; Wsm[lk4 + 2][lrow + 64] = w1.z;
        Wsm[lk4 + 3][lrow] = w0.w; Wsm[lk4 + 3][lrow + 64] = w1.w;
        __syncthreads();

#pragma unroll
        for (int kk = 0; kk < GBK; kk++) {
            F4U av0, av1, av2, av3, bv0, bv1;
            av0.f = *(const float4*)&Asd[kk][tr * 16];
            av1.f = *(const float4*)&Asd[kk][tr * 16 + 4];
            av2.f = *(const float4*)&Asd[kk][tr * 16 + 8];
            av3.f = *(const float4*)&Asd[kk][tr * 16 + 12];
            bv0.f = *(const float4*)&Wsm[kk][tc * 8];
            bv1.f = *(const float4*)&Wsm[kk][tc * 8 + 4];
            unsigned long long ad[8] = { av0.u[0], av0.u[1], av1.u[0], av1.u[1],
                                         av2.u[0], av2.u[1], av3.u[0], av3.u[1] };
            unsigned long long bd[4] = { bv0.u[0], bv0.u[1], bv1.u[0], bv1.u[1] };
#pragma unroll
            for (int i = 0; i < 8; i++)
#pragma unroll
                for (int j = 0; j < 4; j++)
                    acc[i][j] = ffma2(ad[i], bd[j], acc[i][j]);
        }
    }

#pragma unroll
    for (int i = 0; i < 8; i++) {
        float4 c0, c1;
        c0.x = lo32(acc[i][0]); c0.y = hi32(acc[i][0]);
        c0.z = lo32(acc[i][1]); c0.w = hi32(acc[i][1]);
        c1.x = lo32(acc[i][2]); c1.y = hi32(acc[i][2]);
        c1.z = lo32(acc[i][3]); c1.w = hi32(acc[i][3]);
        float* cp = Cmat + (size_t)(bm * GBM + tr * 8 + i) * N + bn * GBN + tc * 8;
        *(float4*)cp       = c0;
        *(float4*)(cp + 4) = c1;
    }
}

// ---------------- 3) Phase A: A_c = k^T diag(wk) v per chunk-head -----------
#define PA_SMEM ((Tq * Kq * 2 + Tq) * 4)   // 66048 B

__global__ __launch_bounds__(256)
void phaseA_kernel(const float* __restrict__ kbuf, const float* __restrict__ vbuf,
                   const float* __restrict__ td)
{
    extern __shared__ float sm[];
    float* ks = sm;                // [128][64]
    float* vs = ks + Tq * Kq;      // [128][64]
    float* pw = vs + Tq * Kq;      // [128]

    int cb = blockIdx.x;           // ((c*B + b)*H + h)
    int h  = cb % Hq;
    int b  = (cb / Hq) % Bq;
    int c  = cb / (Hq * Bq);
    int t  = threadIdx.x;

    const float* kp = kbuf + ((size_t)(b * TTq + c * Tq)) * Cq + h * Kq;
    const float* vp = vbuf + ((size_t)(b * TTq + c * Tq)) * Cq + h * Kq;
#pragma unroll
    for (int l = 0; l < 8; l++) {
        int lin = t + l * 256;
        int row = lin >> 4;
        int c4  = (lin & 15) * 4;
        *(float4*)&ks[row * Kq + c4] = *(const float4*)(kp + (size_t)row * Cq + c4);
        *(float4*)&vs[row * Kq + c4] = *(const float4*)(vp + (size_t)row * Cq + c4);
    }
    float dec = expf(-expf(td[h]));
    if (t == 0) {
        float p = 1.f;
        for (int i = 0; i < Tq; i++) { pw[i] = p; p *= dec; }
    }
    __syncthreads();

    int tp = t >> 4, tq = t & 15;
    float acc[4][4];
#pragma unroll
    for (int i = 0; i < 4; i++)
#pragma unroll
        for (int j = 0; j < 4; j++) acc[i][j] = 0.f;

#pragma unroll 4
    for (int j = 0; j < Tq; j++) {
        float w  = pw[Tq - 1 - j];
        float4 a  = *(const float4*)&ks[j * Kq + tp * 4];
        float4 bb = *(const float4*)&vs[j * Kq + tq * 4];
        float a0 = a.x * w, a1 = a.y * w, a2 = a.z * w, a3 = a.w * w;
        acc[0][0] += a0 * bb.x; acc[0][1] += a0 * bb.y; acc[0][2] += a0 * bb.z; acc[0][3] += a0 * bb.w;
        acc[1][0] += a1 * bb.x; acc[1][1] += a1 * bb.y; acc[1][2] += a1 * bb.z; acc[1][3] += a1 * bb.w;
        acc[2][0] += a2 * bb.x; acc[2][1] += a2 * bb.y; acc[2][2] += a2 * bb.z; acc[2][3] += a2 * bb.w;
        acc[3][0] += a3 * bb.x; acc[3][1] += a3 * bb.y; acc[3][2] += a3 * bb.z; acc[3][3] += a3 * bb.w;
    }
    float* Ap = g_A + (size_t)cb * (Kq * Kq);
#pragma unroll
    for (int i = 0; i < 4; i++)
        *(float4*)&Ap[(tp * 4 + i) * Kq + tq * 4] =
            make_float4(acc[i][0], acc[i][1], acc[i][2], acc[i][3]);
}

// ---------------- 4) Phase B: sequential state scan per (b,h) ---------------
__global__ __launch_bounds__(256)
void phaseB_kernel(const float* __restrict__ td)
{
    int bh = blockIdx.x;           // b*H + h
    int h = bh % Hq;
    int b = bh / Hq;
    int t = threadIdx.x;

    float dec = expf(-expf(td[h]));
    float ws = 1.f;
    for (int i = 0; i < Tq; i++) ws *= dec;    // dec^T

    float S[16];
#pragma unroll
    for (int i = 0; i < 16; i++) S[i] = 0.f;

    for (int c = 0; c < Nq; c++) {
        size_t base = ((size_t)(c * Bq + b) * Hq + h) * (Kq * Kq);
#pragma unroll
        for (int i = 0; i < 16; i++) {
            int e = t + i * 256;
            g_S[base + e] = S[i];
            S[i] = ws * S[i] + g_A[base + e];
        }
    }
}

// ---------------- 5) Phase C: per-chunk output ------------------------------
// out = (r k^T ∘ w_mat) v + (r S) * wb
#define PC_SMEM ((64 * 132 * 2 + Tq * Kq + Kq * Kq + Tq * 129 + Tq) * 4)  // 183296 B

__global__ __launch_bounds__(256)
void phaseC_kernel(const float* __restrict__ rbuf, const float* __restrict__ kbuf,
                   const float* __restrict__ vbuf, const float* __restrict__ td,
                   const float* __restrict__ tf, float* __restrict__ xo)
{
    extern __shared__ float sm[];
    float* rT  = sm;                    // [64][132]  r transposed (k-dim major)
    float* kT  = rT + 64 * 132;         // [64][132]
    float* vs  = kT + 64 * 132;         // [128][64]
    float* Ss  = vs + Tq * Kq;          // [64][64]
    float* att = Ss + Kq * Kq;          // [128][129]
    float* pw  = att + Tq * 129;        // [128]

    int cb = blockIdx.x;
    int h  = cb % Hq;
    int b  = (cb / Hq) % Bq;
    int c  = cb / (Hq * Bq);
    int t  = threadIdx.x;

    const float* rp = rbuf + ((size_t)(b * TTq + c * Tq)) * Cq + h * Kq;
    const float* kp = kbuf + ((size_t)(b * TTq + c * Tq)) * Cq + h * Kq;
    const float* vp = vbuf + ((size_t)(b * TTq + c * Tq)) * Cq + h * Kq;

#pragma unroll
    for (int l = 0; l < 8; l++) {
        int lin = t + l * 256;
        int row = lin >> 4;
        int c4  = (lin & 15) * 4;
        float4 rv = *(const float4*)(rp + (size_t)row * Cq + c4);
        float4 kv = *(const float4*)(kp + (size_t)row * Cq + c4);
        float4 vv = *(const float4*)(vp + (size_t)row * Cq + c4);
        rT[(c4 + 0) * 132 + row] = rv.x; rT[(c4 + 1) * 132 + row] = rv.y;
        rT[(c4 + 2) * 132 + row] = rv.z; rT[(c4 + 3) * 132 + row] = rv.w;
        kT[(c4 + 0) * 132 + row] = kv.x; kT[(c4 + 1) * 132 + row] = kv.y;
        kT[(c4 + 2) * 132 + row] = kv.z; kT[(c4 + 3) * 132 + row] = kv.w;
        *(float4*)&vs[row * Kq + c4] = vv;
    }
    {
        const float* Sp = g_S + (size_t)cb * (Kq * Kq);
#pragma unroll
        for (int l = 0; l < 4; l++) {
            int lin = t + l * 256;
            *(float4*)&Ss[lin * 4] = *(const float4*)(Sp + lin * 4);
        }
    }
    float dec = expf(-expf(td[h]));
    float u   = tf[h];
    if (t == 0) {
        float p = 1.f;
        for (int i = 0; i < Tq; i++) { pw[i] = p; p *= dec; }
    }
    __syncthreads();

    // --- att[i][j] = (r_i . k_j) * w_mat[i][j]  (lower-tri blocks only) ---
    {
        int ti = t >> 4, tj = t & 15;
        int i0 = ti * 8, j0 = tj * 8;
        if (tj <= ti) {
            float acc[8][8];
#pragma unroll
            for (int i = 0; i < 8; i++)
#pragma unroll
                for (int j = 0; j < 8; j++) acc[i][j] = 0.f;
#pragma unroll 4
            for (int k = 0; k < Kq; k++) {
                float4 a0 = *(const float4*)&rT[k * 132 + i0];
                float4 a1 = *(const float4*)&rT[k * 132 + i0 + 4];
                float4 b0 = *(const float4*)&kT[k * 132 + j0];
                float4 b1 = *(const float4*)&kT[k * 132 + j0 + 4];
                float a[8] = { a0.x, a0.y, a0.z, a0.w, a1.x, a1.y, a1.z, a1.w };
                float bb[8] = { b0.x, b0.y, b0.z, b0.w, b1.x, b1.y, b1.z, b1.w };
#pragma unroll
                for (int i = 0; i < 8; i++)
#pragma unroll
                    for (int j = 0; j < 8; j++) acc[i][j] += a[i] * bb[j];
            }
#pragma unroll
            for (int i = 0; i < 8; i++)
#pragma unroll
                for (int j = 0; j < 8; j++) {
                    int gi = i0 + i, gj = j0 + j;
                    float w = (gi > gj) ? pw[gi - gj - 1] : ((gi == gj) ? u : 0.f);
                    att[gi * 129 + gj] = acc[i][j] * w;
                }
        } else {
#pragma unroll
            for (int i = 0; i < 8; i++)
#pragma unroll
                for (int j = 0; j < 8; j++) att[(i0 + i) * 129 + j0 + j] = 0.f;
        }
    }
    __syncthreads();

    // --- out[i][q] = sum_j att[i][j] v[j][q] + (sum_k r[i][k] S[k][q]) * wb[i]
    {
        int i0 = (t >> 4) * 8;
        int q0 = (t & 15) * 4;
        float acc[8][4];
#pragma unroll
        for (int i = 0; i < 8; i++)
#pragma unroll
            for (int q = 0; q < 4; q++) acc[i][q] = 0.f;

#pragma unroll 4
        for (int k = 0; k < Kq; k++) {
            float4 a0 = *(const float4*)&rT[k * 132 + i0];
            float4 a1 = *(const float4*)&rT[k * 132 + i0 + 4];
            float4 s4 = *(const float4*)&Ss[k * Kq + q0];
            float a[8] = { a0.x, a0.y, a0.z, a0.w, a1.x, a1.y, a1.z, a1.w };
#pragma unroll
            for (int i = 0; i < 8; i++) {
                acc[i][0] += a[i] * s4.x; acc[i][1] += a[i] * s4.y;
                acc[i][2] += a[i] * s4.z; acc[i][3] += a[i] * s4.w;
            }
        }
#pragma unroll
        for (int i = 0; i < 8; i++) {
            float wbi = pw[i0 + i];
            acc[i][0] *= wbi; acc[i][1] *= wbi; acc[i][2] *= wbi; acc[i][3] *= wbi;
        }
#pragma unroll 2
        for (int j = 0; j < Tq; j++) {
            float4 v4 = *(const float4*)&vs[j * Kq + q0];
#pragma unroll
            for (int i = 0; i < 8; i++) {
                float aij = att[(i0 + i) * 129 + j];
                acc[i][0] += aij * v4.x; acc[i][1] += aij * v4.y;
                acc[i][2] += aij * v4.z; acc[i][3] += aij * v4.w;
            }
        }
        float* op = xo + ((size_t)(b * TTq + c * Tq)) * Cq + h * Kq;
#pragma unroll
        for (int i = 0; i < 8; i++)
            *(float4*)(op + (size_t)(i0 + i) * Cq + q0) =
                make_float4(acc[i][0], acc[i][1], acc[i][2], acc[i][3]);
    }
}

// ---------------- 6) GroupNorm (per head) + SiLU gate -----------------------
__global__ __launch_bounds__(256)
void gnorm_gate_kernel(const float* __restrict__ lnw, const float* __restrict__ lnb)
{
    int gwarp = (blockIdx.x * 256 + threadIdx.x) >> 5;  // (b*TT+t)*H + h, exact grid
    int lane  = threadIdx.x & 31;
    int h = gwarp & (Hq - 1);
    size_t base = (size_t)gwarp * Kq + lane * 2;

    float2 xo2 = *(const float2*)(g_xr + base);
    float y0 = xo2.x * 0.125f, y1 = xo2.y * 0.125f;
    float s1 = y0 + y1, s2 = y0 * y0 + y1 * y1;
#pragma unroll
    for (int o = 16; o; o >>= 1) {
        s1 += __shfl_xor_sync(0xffffffffu, s1, o);
        s2 += __shfl_xor_sync(0xffffffffu, s2, o);
    }
    float mean = s1 * (1.f / 64.f);
    float var  = s2 * (1.f / 64.f) - mean * mean;
    float rstd = rsqrtf(var + 1e-5f);

    int ci = h * Kq + lane * 2;
    float w0 = lnw[ci], w1 = lnw[ci + 1];
    float b0 = lnb[ci], b1 = lnb[ci + 1];

    float2 g2 = *(const float2*)(g_g + base);
    float sg0 = g2.x / (1.f + expf(-g2.x));
    float sg1 = g2.y / (1.f + expf(-g2.y));

    float2 o2;
    o2.x = ((y0 - mean) * rstd * w0 + b0) * sg0;
    o2.y = ((y1 - mean) * rstd * w1 + b1) * sg1;
    *(float2*)(g_xk + base) = o2;
}

// ---------------- launcher ---------------------------------------------------
extern "C" void kernel_launch(void* const* d_in, const int* in_sizes, int n_in,
                              void* d_out, int out_size)
{
    (void)in_sizes; (void)n_in; (void)out_size;
    const float* x   = (const float*)d_in[0];
    const float* tmk = (const float*)d_in[1];
    const float* tmv = (const float*)d_in[2];
    const float* tmr = (const float*)d_in[3];
    const float* tmg = (const float*)d_in[4];
    const float* td  = (const float*)d_in[5];
    const float* tf  = (const float*)d_in[6];
    const float* Wr  = (const float*)d_in[7];
    const float* Wk  = (const float*)d_in[8];
    const float* Wv  = (const float*)d_in[9];
    const float* Wg  = (const float*)d_in[10];
    const float* Wo  = (const float*)d_in[11];
    const float* lnw = (const float*)d_in[12];
    const float* lnb = (const float*)d_in[13];
    float* out = (float*)d_out;

    float *p_xr, *p_xk, *p_xv, *p_xg, *p_r, *p_k, *p_v, *p_g;
    cudaGetSymbolAddress((void**)&p_xr, g_xr);
    cudaGetSymbolAddress((void**)&p_xk, g_xk);
    cudaGetSymbolAddress((void**)&p_xv, g_xv);
    cudaGetSymbolAddress((void**)&p_xg, g_xg);
    cudaGetSymbolAddress((void**)&p_r,  g_r);
    cudaGetSymbolAddress((void**)&p_k,  g_k);
    cudaGetSymbolAddress((void**)&p_v,  g_v);
    cudaGetSymbolAddress((void**)&p_g,  g_g);

    cudaFuncSetAttribute(phaseA_kernel, cudaFuncAttributeMaxDynamicSharedMemorySize, PA_SMEM);
    cudaFuncSetAttribute(phaseC_kernel, cudaFuncAttributeMaxDynamicSharedMemorySize, PC_SMEM);

    mix_kernel<<<(BT * Cq) / 4 / 256, 256>>>(x, tmr, tmk, tmv, tmg);

    dim3 ggrid(Cq / GBN, BT / GBM);   // (8, 128)
    gemm_nt<<<ggrid, 256>>>(p_xr, Wr, p_r, BT, Cq, Cq);
    gemm_nt<<<ggrid, 256>>>(p_xk, Wk, p_k, BT, Cq, Cq);
    gemm_nt<<<ggrid, 256>>>(p_xv, Wv, p_v, BT, Cq, Cq);
    gemm_nt<<<ggrid, 256>>>(p_xg, Wg, p_g, BT, Cq, Cq);

    phaseA_kernel<<<Nq * Bq * Hq, 256, PA_SMEM>>>(p_k, p_v, td);
    phaseB_kernel<<<Bq * Hq, 256>>>(td);
    phaseC_kernel<<<Nq * Bq * Hq, 256, PC_SMEM>>>(p_r, p_k, p_v, td, tf, p_xr);

    gnorm_gate_kernel<<<(BT * Hq) / 8, 256>>>(lnw, lnb);

    gemm_nt<<<ggrid, 256>>>(p_xk, Wo, out, BT, Cq, Cq);
}

// round 11
// speedup vs baseline: 3.9499x; 3.9499x over previous
#include <cuda_runtime.h>
#include <cuda_bf16.h>
#include <math.h>
#include <stdint.h>

// Problem constants
#define Bq   4
#define TTq  4096
#define Cq   1024
#define Hq   16
#define Kq   64
#define Tq   128
#define Nq   (TTq / Tq)      // 32 chunks
#define BT   (Bq * TTq)      // 16384 rows

// ---------------- scratch (static device arrays; no allocation) -------------
__device__ __nv_bfloat16 g_xrh[BT * Cq], g_xrl[BT * Cq];
__device__ __nv_bfloat16 g_xkh[BT * Cq], g_xkl[BT * Cq];
__device__ __nv_bfloat16 g_xvh[BT * Cq], g_xvl[BT * Cq];
__device__ __nv_bfloat16 g_xgh[BT * Cq], g_xgl[BT * Cq];
__device__ __nv_bfloat16 g_yh [BT * Cq], g_yl [BT * Cq];
__device__ __nv_bfloat16 g_Wh[5 * Cq * Cq], g_Wl[5 * Cq * Cq];
__device__ float g_r [BT * Cq];
__device__ float g_k [BT * Cq];
__device__ float g_v [BT * Cq];
__device__ float g_g [BT * Cq];
__device__ float g_xo[BT * Cq];
__device__ float g_A [Nq * Bq * Hq * Kq * Kq];
__device__ float g_S [Nq * Bq * Hq * Kq * Kq];

// ---------------- PTX helpers (baseline ISA only — no sm_103a features) -----
__device__ __forceinline__ uint32_t smem_u32(const void* p) {
    uint32_t a;
    asm("{ .reg .u64 t; cvta.to.shared.u64 t, %1; cvt.u32.u64 %0, t; }"
        : "=r"(a) : "l"(p));
    return a;
}
__device__ __forceinline__ void cp_async16(uint32_t saddr, const void* gaddr) {
    asm volatile("cp.async.cg.shared.global [%0], [%1], 16;"
                 :: "r"(saddr), "l"(gaddr) : "memory");
}
__device__ __forceinline__ void cp_commit() {
    asm volatile("cp.async.commit_group;" ::: "memory");
}
__device__ __forceinline__ void ldm_x4(uint32_t* r, uint32_t addr) {
    asm volatile("ldmatrix.sync.aligned.m8n8.x4.shared.b16 {%0,%1,%2,%3}, [%4];"
                 : "=r"(r[0]), "=r"(r[1]), "=r"(r[2]), "=r"(r[3]) : "r"(addr));
}
__device__ __forceinline__ void mma_bf16(float* c, const uint32_t* a,
                                         uint32_t b0, uint32_t b1) {
    asm volatile(
        "mma.sync.aligned.m16n8k16.row.col.f32.bf16.bf16.f32 "
        "{%0,%1,%2,%3}, {%4,%5,%6,%7}, {%8,%9}, {%0,%1,%2,%3};"
        : "+f"(c[0]), "+f"(c[1]), "+f"(c[2]), "+f"(c[3])
        : "r"(a[0]), "r"(a[1]), "r"(a[2]), "r"(a[3]), "r"(b0), "r"(b1));
}

// ---------------- 1) time-shift mixing + bf16 hi/lo split -------------------
__device__ __forceinline__ void split_store(float4 o, __nv_bfloat16* hp, __nv_bfloat16* lp) {
    __nv_bfloat16 h0 = __float2bfloat16(o.x), h1 = __float2bfloat16(o.y);
    __nv_bfloat16 h2 = __float2bfloat16(o.z), h3 = __float2bfloat16(o.w);
    __nv_bfloat16 l0 = __float2bfloat16(o.x - __bfloat162float(h0));
    __nv_bfloat16 l1 = __float2bfloat16(o.y - __bfloat162float(h1));
    __nv_bfloat16 l2 = __float2bfloat16(o.z - __bfloat162float(h2));
    __nv_bfloat16 l3 = __float2bfloat16(o.w - __bfloat162float(h3));
    __nv_bfloat162 a; a.x = h0; a.y = h1;
    __nv_bfloat162 b; b.x = h2; b.y = h3;
    *(__nv_bfloat162*)(hp)     = a;
    *(__nv_bfloat162*)(hp + 2) = b;
    a.x = l0; a.y = l1; b.x = l2; b.y = l3;
    *(__nv_bfloat162*)(lp)     = a;
    *(__nv_bfloat162*)(lp + 2) = b;
}

__global__ __launch_bounds__(256)
void mix_split_kernel(const float* __restrict__ x,
                      const float* __restrict__ tmr, const float* __restrict__ tmk,
                      const float* __restrict__ tmv, const float* __restrict__ tmg)
{
    int idx = blockIdx.x * 256 + threadIdx.x;
    int e = idx * 4;
    int c = e & (Cq - 1);
    int bt = e >> 10;
    int tt = bt & (TTq - 1);

    float4 xc = *(const float4*)(x + e);
    float4 xp = make_float4(0.f, 0.f, 0.f, 0.f);
    if (tt != 0) xp = *(const float4*)(x + e - Cq);

    float4 m, o;
    m = *(const float4*)(tmr + c);
    o.x = xc.x * m.x + xp.x * (1.f - m.x); o.y = xc.y * m.y + xp.y * (1.f - m.y);
    o.z = xc.z * m.z + xp.z * (1.f - m.z); o.w = xc.w * m.w + xp.w * (1.f - m.w);
    split_store(o, g_xrh + e, g_xrl + e);
    m = *(const float4*)(tmk + c);
    o.x = xc.x * m.x + xp.x * (1.f - m.x); o.y = xc.y * m.y + xp.y * (1.f - m.y);
    o.z = xc.z * m.z + xp.z * (1.f - m.z); o.w = xc.w * m.w + xp.w * (1.f - m.w);
    split_store(o, g_xkh + e, g_xkl + e);
    m = *(const float4*)(tmv + c);
    o.x = xc.x * m.x + xp.x * (1.f - m.x); o.y = xc.y * m.y + xp.y * (1.f - m.y);
    o.z = xc.z * m.z + xp.z * (1.f - m.z); o.w = xc.w * m.w + xp.w * (1.f - m.w);
    split_store(o, g_xvh + e, g_xvl + e);
    m = *(const float4*)(tmg + c);
    o.x = xc.x * m.x + xp.x * (1.f - m.x); o.y = xc.y * m.y + xp.y * (1.f - m.y);
    o.z = xc.z * m.z + xp.z * (1.f - m.z); o.w = xc.w * m.w + xp.w * (1.f - m.w);
    split_store(o, g_xgh + e, g_xgl + e);
}

__global__ __launch_bounds__(256)
void wsplit_kernel(const float* __restrict__ W, __nv_bfloat16* __restrict__ Wh,
                   __nv_bfloat16* __restrict__ Wl)
{
    int e = (blockIdx.x * 256 + threadIdx.x) * 4;
    float4 w = *(const float4*)(W + e);
    split_store(w, Wh + e, Wl + e);
}

// ---------------- 2) bf16x3 HMMA GEMM ----------------------------------------
// C[m,n] = sum_k Act[m,k] * W[n,k], fp32 accumulate in registers.
// 3 passes: (Ah,Wh) + (Al,Wh) + (Ah,Wl).
// CTA tile 128x128, KB=32 per stage, 2-stage cp.async pipeline.
// smem rows: 32 bf16 (64B) + 16B pad = 80B pitch -> conflict-free ldmatrix.
#define KB      32
#define STG_A   10240                    // 128 rows * 80B
#define STG     20480                    // A + B
#define NKB     96                       // 3 passes * (1024/32)

__global__ __launch_bounds__(256)
void gemm_hmma(const __nv_bfloat16* __restrict__ Ah,
               const __nv_bfloat16* __restrict__ Al,
               const __nv_bfloat16* __restrict__ Wh,
               const __nv_bfloat16* __restrict__ Wl,
               float* __restrict__ Cmat)
{
    __shared__ __align__(16) char smem[2 * STG];
    uint32_t sb = smem_u32(smem);

    int t = threadIdx.x;
    int w = t >> 5, lane = t & 31;
    int wm = w >> 2;            // 0..1  (64-row slab)
    int wn = w & 3;             // 0..3  (32-col slab)
    int bm = blockIdx.y, bn = blockIdx.x;

    const __nv_bfloat16* Asrc[3] = { Ah, Al, Ah };
    const __nv_bfloat16* Wsrc[3] = { Wh, Wh, Wl };

    // cp.async geometry: 2 A-chunks + 2 B-chunks of 16B per thread per stage
    uint32_t a_so[2], b_so[2];
    size_t   a_go[2], b_go[2];
#pragma unroll
    for (int i = 0; i < 2; i++) {
        int lin = t + i * 256;
        int row = lin >> 2, c16 = lin & 3;
        a_so[i] = (uint32_t)(row * 80 + c16 * 16);
        b_so[i] = a_so[i];
        a_go[i] = (size_t)(bm * 128 + row) * Cq + c16 * 8;
        b_go[i] = (size_t)(bn * 128 + row) * Cq + c16 * 8;
    }

    // ldmatrix per-lane base offsets
    int lr = lane & 7, sel = lane >> 3;
    // A tile m16k16 as 4 8x8 matrices: sel0 rows0-7 k0-7, sel1 rows8-15 k0-7,
    // sel2 rows0-7 k8-15, sel3 rows8-15 k8-15
    uint32_t a_lb = (uint32_t)((wm * 64 + lr + (sel & 1) * 8) * 80 + ((sel >> 1) & 1) * 16);
    // B tile n16k16: sel0 cols0-7 k0-7, sel1 cols0-7 k8-15, sel2 cols8-15 k0-7,
    // sel3 cols8-15 k8-15
    uint32_t b_lb = (uint32_t)((wn * 32 + lr + (sel >> 1) * 8) * 80 + (sel & 1) * 16);

    float C[4][4][4];
#pragma unroll
    for (int i = 0; i < 4; i++)
#pragma unroll
        for (int j = 0; j < 4; j++)
#pragma unroll
            for (int q = 0; q < 4; q++) C[i][j][q] = 0.f;

    // prologue: stage 0
    {
        const __nv_bfloat16* Ap = Asrc[0];
        const __nv_bfloat16* Bp = Wsrc[0];
#pragma unroll
        for (int i = 0; i < 2; i++) {
            cp_async16(sb + a_so[i], Ap + a_go[i]);
            cp_async16(sb + STG_A + b_so[i], Bp + b_go[i]);
        }
        cp_commit();
    }

    for (int kb = 0; kb < NKB; kb++) {
        if (kb + 1 < NKB) {
            int p = (kb + 1) >> 5, k0 = ((kb + 1) & 31) * KB;
            const __nv_bfloat16* Ap = Asrc[p];
            const __nv_bfloat16* Bp = Wsrc[p];
            uint32_t st = sb + ((kb + 1) & 1) * STG;
#pragma unroll
            for (int i = 0; i < 2; i++) {
                cp_async16(st + a_so[i], Ap + a_go[i] + k0);
                cp_async16(st + STG_A + b_so[i], Bp + b_go[i] + k0);
            }
            cp_commit();
            asm volatile("cp.async.wait_group 1;" ::: "memory");
        } else {
            asm volatile("cp.async.wait_group 0;" ::: "memory");
        }
        __syncthreads();

        uint32_t AS = sb + (kb & 1) * STG;
        uint32_t BS = AS + STG_A;
#pragma unroll
        for (int s = 0; s < 2; s++) {
            uint32_t afr[4][4], bfr[2][4];
#pragma unroll
            for (int mt = 0; mt < 4; mt++)
                ldm_x4(afr[mt], AS + a_lb + (uint32_t)(mt * 16 * 80 + s * 32));
#pragma unroll
            for (int g = 0; g < 2; g++)
                ldm_x4(bfr[g], BS + b_lb + (uint32_t)(g * 16 * 80 + s * 32));
#pragma unroll
            for (int mt = 0; mt < 4; mt++) {
#pragma unroll
                for (int g = 0; g < 2; g++) {
                    mma_bf16(C[mt][2 * g],     afr[mt], bfr[g][0], bfr[g][1]);
                    mma_bf16(C[mt][2 * g + 1], afr[mt], bfr[g][2], bfr[g][3]);
                }
            }
        }
        __syncthreads();
    }

    // epilogue: direct fp32 stores (float2 per fragment pair)
    int row0 = bm * 128 + wm * 64 + (lane >> 2);
    int col0 = bn * 128 + wn * 32 + (lane & 3) * 2;
#pragma unroll
    for (int mt = 0; mt < 4; mt++) {
#pragma unroll
        for (int nt = 0; nt < 4; nt++) {
            float* p0 = Cmat + (size_t)(row0 + mt * 16) * Cq + col0 + nt * 8;
            float* p1 = p0 + 8 * Cq;
            float2 v0 = make_float2(C[mt][nt][0], C[mt][nt][1]);
            float2 v1 = make_float2(C[mt][nt][2], C[mt][nt][3]);
            *(float2*)p0 = v0;
            *(float2*)p1 = v1;
        }
    }
}

// ---------------- 3) Phase A: A_c = k^T diag(wk) v per chunk-head -----------
#define PA_SMEM ((Tq * Kq * 2 + Tq) * 4)   // 66048 B

__global__ __launch_bounds__(256)
void phaseA_kernel(const float* __restrict__ kbuf, const float* __restrict__ vbuf,
                   const float* __restrict__ td)
{
    extern __shared__ float sm[];
    float* ks = sm;
    float* vs = ks + Tq * Kq;
    float* pw = vs + Tq * Kq;

    int cb = blockIdx.x;
    int h  = cb % Hq;
    int b  = (cb / Hq) % Bq;
    int c  = cb / (Hq * Bq);
    int t  = threadIdx.x;

    const float* kp = kbuf + ((size_t)(b * TTq + c * Tq)) * Cq + h * Kq;
    const float* vp = vbuf + ((size_t)(b * TTq + c * Tq)) * Cq + h * Kq;
#pragma unroll
    for (int l = 0; l < 8; l++) {
        int lin = t + l * 256;
        int row = lin >> 4;
        int c4  = (lin & 15) * 4;
        *(float4*)&ks[row * Kq + c4] = *(const float4*)(kp + (size_t)row * Cq + c4);
        *(float4*)&vs[row * Kq + c4] = *(const float4*)(vp + (size_t)row * Cq + c4);
    }
    float dec = expf(-expf(td[h]));
    if (t == 0) {
        float p = 1.f;
        for (int i = 0; i < Tq; i++) { pw[i] = p; p *= dec; }
    }
    __syncthreads();

    int tp = t >> 4, tq = t & 15;
    float acc[4][4];
#pragma unroll
    for (int i = 0; i < 4; i++)
#pragma unroll
        for (int j = 0; j < 4; j++) acc[i][j] = 0.f;

#pragma unroll 4
    for (int j = 0; j < Tq; j++) {
        float w  = pw[Tq - 1 - j];
        float4 a  = *(const float4*)&ks[j * Kq + tp * 4];
        float4 bb = *(const float4*)&vs[j * Kq + tq * 4];
        float a0 = a.x * w, a1 = a.y * w, a2 = a.z * w, a3 = a.w * w;
        acc[0][0] += a0 * bb.x; acc[0][1] += a0 * bb.y; acc[0][2] += a0 * bb.z; acc[0][3] += a0 * bb.w;
        acc[1][0] += a1 * bb.x; acc[1][1] += a1 * bb.y; acc[1][2] += a1 * bb.z; acc[1][3] += a1 * bb.w;
        acc[2][0] += a2 * bb.x; acc[2][1] += a2 * bb.y; acc[2][2] += a2 * bb.z; acc[2][3] += a2 * bb.w;
        acc[3][0] += a3 * bb.x; acc[3][1] += a3 * bb.y; acc[3][2] += a3 * bb.z; acc[3][3] += a3 * bb.w;
    }
    float* Ap = g_A + (size_t)cb * (Kq * Kq);
#pragma unroll
    for (int i = 0; i < 4; i++)
        *(float4*)&Ap[(tp * 4 + i) * Kq + tq * 4] =
            make_float4(acc[i][0], acc[i][1], acc[i][2], acc[i][3]);
}

// ---------------- 4) Phase B: sequential state scan per (b,h) ---------------
__global__ __launch_bounds__(256)
void phaseB_kernel(const float* __restrict__ td)
{
    int bh = blockIdx.x;
    int h = bh % Hq;
    int b = bh / Hq;
    int t = threadIdx.x;

    float dec = expf(-expf(td[h]));
    float ws = 1.f;
    for (int i = 0; i < Tq; i++) ws *= dec;

    float S[16];
#pragma unroll
    for (int i = 0; i < 16; i++) S[i] = 0.f;

    for (int c = 0; c < Nq; c++) {
        size_t base = ((size_t)(c * Bq + b) * Hq + h) * (Kq * Kq);
#pragma unroll
        for (int i = 0; i < 16; i++) {
            int e = t + i * 256;
            g_S[base + e] = S[i];
            S[i] = ws * S[i] + g_A[base + e];
        }
    }
}

// ---------------- 5) Phase C: per-chunk output ------------------------------
#define PC_SMEM ((64 * 132 * 2 + Tq * Kq + Kq * Kq + Tq * 129 + Tq) * 4)  // 183296 B

__global__ __launch_bounds__(256)
void phaseC_kernel(const float* __restrict__ rbuf, const float* __restrict__ kbuf,
                   const float* __restrict__ vbuf, const float* __restrict__ td,
                   const float* __restrict__ tf, float* __restrict__ xo)
{
    extern __shared__ float sm[];
    float* rT  = sm;
    float* kT  = rT + 64 * 132;
    float* vs  = kT + 64 * 132;
    float* Ss  = vs + Tq * Kq;
    float* att = Ss + Kq * Kq;
    float* pw  = att + Tq * 129;

    int cb = blockIdx.x;
    int h  = cb % Hq;
    int b  = (cb / Hq) % Bq;
    int c  = cb / (Hq * Bq);
    int t  = threadIdx.x;

    const float* rp = rbuf + ((size_t)(b * TTq + c * Tq)) * Cq + h * Kq;
    const float* kp = kbuf + ((size_t)(b * TTq + c * Tq)) * Cq + h * Kq;
    const float* vp = vbuf + ((size_t)(b * TTq + c * Tq)) * Cq + h * Kq;

#pragma unroll
    for (int l = 0; l < 8; l++) {
        int lin = t + l * 256;
        int row = lin >> 4;
        int c4  = (lin & 15) * 4;
        float4 rv = *(const float4*)(rp + (size_t)row * Cq + c4);
        float4 kv = *(const float4*)(kp + (size_t)row * Cq + c4);
        float4 vv = *(const float4*)(vp + (size_t)row * Cq + c4);
        rT[(c4 + 0) * 132 + row] = rv.x; rT[(c4 + 1) * 132 + row] = rv.y;
        rT[(c4 + 2) * 132 + row] = rv.z; rT[(c4 + 3) * 132 + row] = rv.w;
        kT[(c4 + 0) * 132 + row] = kv.x; kT[(c4 + 1) * 132 + row] = kv.y;
        kT[(c4 + 2) * 132 + row] = kv.z; kT[(c4 + 3) * 132 + row] = kv.w;
        *(float4*)&vs[row * Kq + c4] = vv;
    }
    {
        const float* Sp = g_S + (size_t)cb * (Kq * Kq);
#pragma unroll
        for (int l = 0; l < 4; l++) {
            int lin = t + l * 256;
            *(float4*)&Ss[lin * 4] = *(const float4*)(Sp + lin * 4);
        }
    }
    float dec = expf(-expf(td[h]));
    float u   = tf[h];
    if (t == 0) {
        float p = 1.f;
        for (int i = 0; i < Tq; i++) { pw[i] = p; p *= dec; }
    }
    __syncthreads();

    {
        int ti = t >> 4, tj = t & 15;
        int i0 = ti * 8, j0 = tj * 8;
        if (tj <= ti) {
            float acc[8][8];
#pragma unroll
            for (int i = 0; i < 8; i++)
#pragma unroll
                for (int j = 0; j < 8; j++) acc[i][j] = 0.f;
#pragma unroll 4
            for (int k = 0; k < Kq; k++) {
                float4 a0 = *(const float4*)&rT[k * 132 + i0];
                float4 a1 = *(const float4*)&rT[k * 132 + i0 + 4];
                float4 b0 = *(const float4*)&kT[k * 132 + j0];
                float4 b1 = *(const float4*)&kT[k * 132 + j0 + 4];
                float a[8] = { a0.x, a0.y, a0.z, a0.w, a1.x, a1.y, a1.z, a1.w };
                float bb[8] = { b0.x, b0.y, b0.z, b0.w, b1.x, b1.y, b1.z, b1.w };
#pragma unroll
                for (int i = 0; i < 8; i++)
#pragma unroll
                    for (int j = 0; j < 8; j++) acc[i][j] += a[i] * bb[j];
            }
#pragma unroll
            for (int i = 0; i < 8; i++)
#pragma unroll
                for (int j = 0; j < 8; j++) {
                    int gi = i0 + i, gj = j0 + j;
                    float w = (gi > gj) ? pw[gi - gj - 1] : ((gi == gj) ? u : 0.f);
                    att[gi * 129 + gj] = acc[i][j] * w;
                }
        } else {
#pragma unroll
            for (int i = 0; i < 8; i++)
#pragma unroll
                for (int j = 0; j < 8; j++) att[(i0 + i) * 129 + j0 + j] = 0.f;
        }
    }
    __syncthreads();

    {
        int i0 = (t >> 4) * 8;
        int q0 = (t & 15) * 4;
        float acc[8][4];
#pragma unroll
        for (int i = 0; i < 8; i++)
#pragma unroll
            for (int q = 0; q < 4; q++) acc[i][q] = 0.f;

#pragma unroll 4
        for (int k = 0; k < Kq; k++) {
            float4 a0 = *(const float4*)&rT[k * 132 + i0];
            float4 a1 = *(const float4*)&rT[k * 132 + i0 + 4];
            float4 s4 = *(const float4*)&Ss[k * Kq + q0];
            float a[8] = { a0.x, a0.y, a0.z, a0.w, a1.x, a1.y, a1.z, a1.w };
#pragma unroll
            for (int i = 0; i < 8; i++) {
                acc[i][0] += a[i] * s4.x; acc[i][1] += a[i] * s4.y;
                acc[i][2] += a[i] * s4.z; acc[i][3] += a[i] * s4.w;
            }
        }
#pragma unroll
        for (int i = 0; i < 8; i++) {
            float wbi = pw[i0 + i];
            acc[i][0] *= wbi; acc[i][1] *= wbi; acc[i][2] *= wbi; acc[i][3] *= wbi;
        }
#pragma unroll 2
        for (int j = 0; j < Tq; j++) {
            float4 v4 = *(const float4*)&vs[j * Kq + q0];
#pragma unroll
            for (int i = 0; i < 8; i++) {
                float aij = att[(i0 + i) * 129 + j];
                acc[i][0] += aij * v4.x; acc[i][1] += aij * v4.y;
                acc[i][2] += aij * v4.z; acc[i][3] += aij * v4.w;
            }
        }
        float* op = xo + ((size_t)(b * TTq + c * Tq)) * Cq + h * Kq;
#pragma unroll
        for (int i = 0; i < 8; i++)
            *(float4*)(op + (size_t)(i0 + i) * Cq + q0) =
                make_float4(acc[i][0], acc[i][1], acc[i][2], acc[i][3]);
    }
}

// ---------------- 6) GroupNorm + SiLU gate + bf16 split ---------------------
__global__ __launch_bounds__(256)
void gnorm_gate_kernel(const float* __restrict__ lnw, const float* __restrict__ lnb)
{
    int gwarp = (blockIdx.x * 256 + threadIdx.x) >> 5;
    int lane  = threadIdx.x & 31;
    int h = gwarp & (Hq - 1);
    size_t base = (size_t)gwarp * Kq + lane * 2;

    float2 xo2 = *(const float2*)(g_xo + base);
    float y0 = xo2.x * 0.125f, y1 = xo2.y * 0.125f;
    float s1 = y0 + y1, s2 = y0 * y0 + y1 * y1;
#pragma unroll
    for (int o = 16; o; o >>= 1) {
        s1 += __shfl_xor_sync(0xffffffffu, s1, o);
        s2 += __shfl_xor_sync(0xffffffffu, s2, o);
    }
    float mean = s1 * (1.f / 64.f);
    float var  = s2 * (1.f / 64.f) - mean * mean;
    float rstd = rsqrtf(var + 1e-5f);

    int ci = h * Kq + lane * 2;
    float w0 = lnw[ci], w1 = lnw[ci + 1];
    float b0 = lnb[ci], b1 = lnb[ci + 1];

    float2 g2 = *(const float2*)(g_g + base);
    float sg0 = g2.x / (1.f + expf(-g2.x));
    float sg1 = g2.y / (1.f + expf(-g2.y));

    float o0 = ((y0 - mean) * rstd * w0 + b0) * sg0;
    float o1 = ((y1 - mean) * rstd * w1 + b1) * sg1;

    __nv_bfloat16 h0 = __float2bfloat16(o0), h1 = __float2bfloat16(o1);
    __nv_bfloat16 l0 = __float2bfloat16(o0 - __bfloat162float(h0));
    __nv_bfloat16 l1 = __float2bfloat16(o1 - __bfloat162float(h1));
    __nv_bfloat162 hv; hv.x = h0; hv.y = h1;
    __nv_bfloat162 lv; lv.x = l0; lv.y = l1;
    *(__nv_bfloat162*)(g_yh + base) = hv;
    *(__nv_bfloat162*)(g_yl + base) = lv;
}

// ---------------- launcher ---------------------------------------------------
extern "C" void kernel_launch(void* const* d_in, const int* in_sizes, int n_in,
                              void* d_out, int out_size)
{
    (void)in_sizes; (void)n_in; (void)out_size;
    const float* x   = (const float*)d_in[0];
    const float* tmk = (const float*)d_in[1];
    const float* tmv = (const float*)d_in[2];
    const float* tmr = (const float*)d_in[3];
    const float* tmg = (const float*)d_in[4];
    const float* td  = (const float*)d_in[5];
    const float* tf  = (const float*)d_in[6];
    const float* Wr  = (const float*)d_in[7];
    const float* Wk  = (const float*)d_in[8];
    const float* Wv  = (const float*)d_in[9];
    const float* Wg  = (const float*)d_in[10];
    const float* Wo  = (const float*)d_in[11];
    const float* lnw = (const float*)d_in[12];
    const float* lnb = (const float*)d_in[13];
    float* out = (float*)d_out;

    __nv_bfloat16 *p_xrh, *p_xrl, *p_xkh, *p_xkl, *p_xvh, *p_xvl, *p_xgh, *p_xgl;
    __nv_bfloat16 *p_yh, *p_yl, *p_Wh, *p_Wl;
    float *p_r, *p_k, *p_v, *p_g, *p_xo;
    cudaGetSymbolAddress((void**)&p_xrh, g_xrh);
    cudaGetSymbolAddress((void**)&p_xrl, g_xrl);
    cudaGetSymbolAddress((void**)&p_xkh, g_xkh);
    cudaGetSymbolAddress((void**)&p_xkl, g_xkl);
    cudaGetSymbolAddress((void**)&p_xvh, g_xvh);
    cudaGetSymbolAddress((void**)&p_xvl, g_xvl);
    cudaGetSymbolAddress((void**)&p_xgh, g_xgh);
    cudaGetSymbolAddress((void**)&p_xgl, g_xgl);
    cudaGetSymbolAddress((void**)&p_yh,  g_yh);
    cudaGetSymbolAddress((void**)&p_yl,  g_yl);
    cudaGetSymbolAddress((void**)&p_Wh,  g_Wh);
    cudaGetSymbolAddress((void**)&p_Wl,  g_Wl);
    cudaGetSymbolAddress((void**)&p_r,   g_r);
    cudaGetSymbolAddress((void**)&p_k,   g_k);
    cudaGetSymbolAddress((void**)&p_v,   g_v);
    cudaGetSymbolAddress((void**)&p_g,   g_g);
    cudaGetSymbolAddress((void**)&p_xo,  g_xo);

    cudaFuncSetAttribute(phaseA_kernel, cudaFuncAttributeMaxDynamicSharedMemorySize, PA_SMEM);
    cudaFuncSetAttribute(phaseC_kernel, cudaFuncAttributeMaxDynamicSharedMemorySize, PC_SMEM);

    mix_split_kernel<<<(BT * Cq) / 4 / 256, 256>>>(x, tmr, tmk, tmv, tmg);

    const int WGRID = (Cq * Cq) / 4 / 256;
    wsplit_kernel<<<WGRID, 256>>>(Wr, p_Wh + 0 * Cq * Cq, p_Wl + 0 * Cq * Cq);
    wsplit_kernel<<<WGRID, 256>>>(Wk, p_Wh + 1 * Cq * Cq, p_Wl + 1 * Cq * Cq);
    wsplit_kernel<<<WGRID, 256>>>(Wv, p_Wh + 2 * Cq * Cq, p_Wl + 2 * Cq * Cq);
    wsplit_kernel<<<WGRID, 256>>>(Wg, p_Wh + 3 * Cq * Cq, p_Wl + 3 * Cq * Cq);
    wsplit_kernel<<<WGRID, 256>>>(Wo, p_Wh + 4 * Cq * Cq, p_Wl + 4 * Cq * Cq);

    dim3 ggrid(Cq / 128, BT / 128);   // (8, 128)
    gemm_hmma<<<ggrid, 256>>>(p_xrh, p_xrl, p_Wh + 0 * Cq * Cq, p_Wl + 0 * Cq * Cq, p_r);
    gemm_hmma<<<ggrid, 256>>>(p_xkh, p_xkl, p_Wh + 1 * Cq * Cq, p_Wl + 1 * Cq * Cq, p_k);
    gemm_hmma<<<ggrid, 256>>>(p_xvh, p_xvl, p_Wh + 2 * Cq * Cq, p_Wl + 2 * Cq * Cq, p_v);
    gemm_hmma<<<ggrid, 256>>>(p_xgh, p_xgl, p_Wh + 3 * Cq * Cq, p_Wl + 3 * Cq * Cq, p_g);

    phaseA_kernel<<<Nq * Bq * Hq, 256, PA_SMEM>>>(p_k, p_v, td);
    phaseB_kernel<<<Bq * Hq, 256>>>(td);
    phaseC_kernel<<<Nq * Bq * Hq, 256, PC_SMEM>>>(p_r, p_k, p_v, td, tf, p_xo);

    gnorm_gate_kernel<<<(BT * Hq) / 8, 256>>>(lnw, lnb);

    gemm_hmma<<<ggrid, 256>>>(p_yh, p_yl, p_Wh + 4 * Cq * Cq, p_Wl + 4 * Cq * Cq, out);
}

// round 12
// speedup vs baseline: 4.7596x; 1.2050x over previous
#include <cuda_runtime.h>
#include <cuda_bf16.h>
#include <math.h>
#include <stdint.h>

// Problem constants
#define Bq   4
#define TTq  4096
#define Cq   1024
#define Hq   16
#define Kq   64
#define Tq   128
#define Nq   (TTq / Tq)      // 32 chunks
#define BT   (Bq * TTq)      // 16384 rows

// ---------------- scratch (static device arrays; no allocation) -------------
__device__ __nv_bfloat16 g_xrh[BT * Cq], g_xrl[BT * Cq];
__device__ __nv_bfloat16 g_xkh[BT * Cq], g_xkl[BT * Cq];
__device__ __nv_bfloat16 g_xvh[BT * Cq], g_xvl[BT * Cq];
__device__ __nv_bfloat16 g_xgh[BT * Cq], g_xgl[BT * Cq];
__device__ __nv_bfloat16 g_yh [BT * Cq], g_yl [BT * Cq];
__device__ __nv_bfloat16 g_Wh[5 * Cq * Cq], g_Wl[5 * Cq * Cq];
__device__ float g_r [BT * Cq];
__device__ float g_k [BT * Cq];
__device__ float g_v [BT * Cq];
__device__ float g_g [BT * Cq];
__device__ float g_xo[BT * Cq];
__device__ float g_A [Nq * Bq * Hq * Kq * Kq];
__device__ float g_S [Nq * Bq * Hq * Kq * Kq];

// ---------------- PTX helpers (baseline ISA only) ----------------------------
__device__ __forceinline__ uint32_t smem_u32(const void* p) {
    uint32_t a;
    asm("{ .reg .u64 t; cvta.to.shared.u64 t, %1; cvt.u32.u64 %0, t; }"
        : "=r"(a) : "l"(p));
    return a;
}
__device__ __forceinline__ void cp_async16(uint32_t saddr, const void* gaddr) {
    asm volatile("cp.async.cg.shared.global [%0], [%1], 16;"
                 :: "r"(saddr), "l"(gaddr) : "memory");
}
__device__ __forceinline__ void cp_commit() {
    asm volatile("cp.async.commit_group;" ::: "memory");
}
__device__ __forceinline__ void ldm_x4(uint32_t* r, uint32_t addr) {
    asm volatile("ldmatrix.sync.aligned.m8n8.x4.shared.b16 {%0,%1,%2,%3}, [%4];"
                 : "=r"(r[0]), "=r"(r[1]), "=r"(r[2]), "=r"(r[3]) : "r"(addr));
}
__device__ __forceinline__ void mma_bf16(float* c, const uint32_t* a,
                                         uint32_t b0, uint32_t b1) {
    asm volatile(
        "mma.sync.aligned.m16n8k16.row.col.f32.bf16.bf16.f32 "
        "{%0,%1,%2,%3}, {%4,%5,%6,%7}, {%8,%9}, {%0,%1,%2,%3};"
        : "+f"(c[0]), "+f"(c[1]), "+f"(c[2]), "+f"(c[3])
        : "r"(a[0]), "r"(a[1]), "r"(a[2]), "r"(a[3]), "r"(b0), "r"(b1));
}

// ---------------- 1) time-shift mixing + bf16 hi/lo split -------------------
__device__ __forceinline__ void split_store(float4 o, __nv_bfloat16* hp, __nv_bfloat16* lp) {
    __nv_bfloat16 h0 = __float2bfloat16(o.x), h1 = __float2bfloat16(o.y);
    __nv_bfloat16 h2 = __float2bfloat16(o.z), h3 = __float2bfloat16(o.w);
    __nv_bfloat16 l0 = __float2bfloat16(o.x - __bfloat162float(h0));
    __nv_bfloat16 l1 = __float2bfloat16(o.y - __bfloat162float(h1));
    __nv_bfloat16 l2 = __float2bfloat16(o.z - __bfloat162float(h2));
    __nv_bfloat16 l3 = __float2bfloat16(o.w - __bfloat162float(h3));
    __nv_bfloat162 a; a.x = h0; a.y = h1;
    __nv_bfloat162 b; b.x = h2; b.y = h3;
    *(__nv_bfloat162*)(hp)     = a;
    *(__nv_bfloat162*)(hp + 2) = b;
    a.x = l0; a.y = l1; b.x = l2; b.y = l3;
    *(__nv_bfloat162*)(lp)     = a;
    *(__nv_bfloat162*)(lp + 2) = b;
}

__global__ __launch_bounds__(256)
void mix_split_kernel(const float* __restrict__ x,
                      const float* __restrict__ tmr, const float* __restrict__ tmk,
                      const float* __restrict__ tmv, const float* __restrict__ tmg)
{
    int idx = blockIdx.x * 256 + threadIdx.x;
    int e = idx * 4;
    int c = e & (Cq - 1);
    int bt = e >> 10;
    int tt = bt & (TTq - 1);

    float4 xc = *(const float4*)(x + e);
    float4 xp = make_float4(0.f, 0.f, 0.f, 0.f);
    if (tt != 0) xp = *(const float4*)(x + e - Cq);

    float4 m, o;
    m = *(const float4*)(tmr + c);
    o.x = xc.x * m.x + xp.x * (1.f - m.x); o.y = xc.y * m.y + xp.y * (1.f - m.y);
    o.z = xc.z * m.z + xp.z * (1.f - m.z); o.w = xc.w * m.w + xp.w * (1.f - m.w);
    split_store(o, g_xrh + e, g_xrl + e);
    m = *(const float4*)(tmk + c);
    o.x = xc.x * m.x + xp.x * (1.f - m.x); o.y = xc.y * m.y + xp.y * (1.f - m.y);
    o.z = xc.z * m.z + xp.z * (1.f - m.z); o.w = xc.w * m.w + xp.w * (1.f - m.w);
    split_store(o, g_xkh + e, g_xkl + e);
    m = *(const float4*)(tmv + c);
    o.x = xc.x * m.x + xp.x * (1.f - m.x); o.y = xc.y * m.y + xp.y * (1.f - m.y);
    o.z = xc.z * m.z + xp.z * (1.f - m.z); o.w = xc.w * m.w + xp.w * (1.f - m.w);
    split_store(o, g_xvh + e, g_xvl + e);
    m = *(const float4*)(tmg + c);
    o.x = xc.x * m.x + xp.x * (1.f - m.x); o.y = xc.y * m.y + xp.y * (1.f - m.y);
    o.z = xc.z * m.z + xp.z * (1.f - m.z); o.w = xc.w * m.w + xp.w * (1.f - m.w);
    split_store(o, g_xgh + e, g_xgl + e);
}

// all 5 weight matrices in one launch
__global__ __launch_bounds__(256)
void wsplit5_kernel(const float* __restrict__ W0, const float* __restrict__ W1,
                    const float* __restrict__ W2, const float* __restrict__ W3,
                    const float* __restrict__ W4,
                    __nv_bfloat16* __restrict__ Wh, __nv_bfloat16* __restrict__ Wl)
{
    int m = blockIdx.y;
    const float* W = (m == 0) ? W0 : (m == 1) ? W1 : (m == 2) ? W2 : (m == 3) ? W3 : W4;
    int e = (blockIdx.x * 256 + threadIdx.x) * 4;
    float4 w = *(const float4*)(W + e);
    split_store(w, Wh + (size_t)m * Cq * Cq + e, Wl + (size_t)m * Cq * Cq + e);
}

// ---------------- 2) bf16x3 HMMA GEMM, fused 3-combo K-loop ------------------
// C = Ah*Wh^T + Ah*Wl^T + Al*Wh^T, fp32 register accumulate.
// CTA tile 128x128, KB=32 per stage; stage holds Ah,Al,Wh,Wl tiles (40KB);
// 2-stage cp.async pipeline in dynamic smem (80KB), 2 CTAs/SM.
// smem rows: 32 bf16 (64B) + 16B pad = 80B pitch -> conflict-free ldmatrix.
#define KB      32
#define TILE_B  10240                    // 128 rows * 80B
#define STG4    (4 * TILE_B)             // 40960: Ah|Al|Wh|Wl
#define GSMEM   (2 * STG4)               // 81920
#define NKB     32                       // 1024 / KB

__global__ __launch_bounds__(256, 2)
void gemm_hmma(const __nv_bfloat16* __restrict__ Ah,
               const __nv_bfloat16* __restrict__ Al,
               const __nv_bfloat16* __restrict__ Wh,
               const __nv_bfloat16* __restrict__ Wl,
               float* __restrict__ Cmat)
{
    extern __shared__ __align__(16) char smem[];
    uint32_t sb = smem_u32(smem);

    int t = threadIdx.x;
    int w = t >> 5, lane = t & 31;
    int wm = w >> 2;            // 0..1  (64-row slab)
    int wn = w & 3;             // 0..3  (32-col slab)
    int bm = blockIdx.y, bn = blockIdx.x;

    // cp.async geometry: per stage, per thread: 2 chunks per tile x 4 tiles
    uint32_t so[2]; size_t a_go[2], b_go[2];
#pragma unroll
    for (int i = 0; i < 2; i++) {
        int lin = t + i * 256;
        int row = lin >> 2, c16 = lin & 3;
        so[i]   = (uint32_t)(row * 80 + c16 * 16);
        a_go[i] = (size_t)(bm * 128 + row) * Cq + c16 * 8;
        b_go[i] = (size_t)(bn * 128 + row) * Cq + c16 * 8;
    }

    // ldmatrix per-lane base offsets (within one tile)
    int lr = lane & 7, sel = lane >> 3;
    uint32_t a_lb = (uint32_t)((wm * 64 + lr + (sel & 1) * 8) * 80 + ((sel >> 1) & 1) * 16);
    uint32_t b_lb = (uint32_t)((wn * 32 + lr + (sel >> 1) * 8) * 80 + (sel & 1) * 16);

    float C[4][4][4];
#pragma unroll
    for (int i = 0; i < 4; i++)
#pragma unroll
        for (int j = 0; j < 4; j++)
#pragma unroll
            for (int q = 0; q < 4; q++) C[i][j][q] = 0.f;

    // prologue: stage 0 <- kb 0
    {
        uint32_t st = sb;
#pragma unroll
        for (int i = 0; i < 2; i++) {
            cp_async16(st + so[i],              Ah + a_go[i]);
            cp_async16(st + TILE_B + so[i],     Al + a_go[i]);
            cp_async16(st + 2 * TILE_B + so[i], Wh + b_go[i]);
            cp_async16(st + 3 * TILE_B + so[i], Wl + b_go[i]);
        }
        cp_commit();
    }

    for (int kb = 0; kb < NKB; kb++) {
        if (kb + 1 < NKB) {
            int k0 = (kb + 1) * KB;
            uint32_t st = sb + ((kb + 1) & 1) * STG4;
#pragma unroll
            for (int i = 0; i < 2; i++) {
                cp_async16(st + so[i],              Ah + a_go[i] + k0);
                cp_async16(st + TILE_B + so[i],     Al + a_go[i] + k0);
                cp_async16(st + 2 * TILE_B + so[i], Wh + b_go[i] + k0);
                cp_async16(st + 3 * TILE_B + so[i], Wl + b_go[i] + k0);
            }
            cp_commit();
            asm volatile("cp.async.wait_group 1;" ::: "memory");
        } else {
            asm volatile("cp.async.wait_group 0;" ::: "memory");
        }
        __syncthreads();

        uint32_t base = sb + (kb & 1) * STG4;
#pragma unroll
        for (int s = 0; s < 2; s++) {
            uint32_t aH[4][4], bH[2][4], bL[2][4];
            // combo 1: Ah * Wh
#pragma unroll
            for (int mt = 0; mt < 4; mt++)
                ldm_x4(aH[mt], base + a_lb + (uint32_t)(mt * 16 * 80 + s * 32));
#pragma unroll
            for (int g = 0; g < 2; g++)
                ldm_x4(bH[g], base + 2 * TILE_B + b_lb + (uint32_t)(g * 16 * 80 + s * 32));
#pragma unroll
            for (int mt = 0; mt < 4; mt++)
#pragma unroll
                for (int g = 0; g < 2; g++) {
                    mma_bf16(C[mt][2 * g],     aH[mt], bH[g][0], bH[g][1]);
                    mma_bf16(C[mt][2 * g + 1], aH[mt], bH[g][2], bH[g][3]);
                }
            // combo 2: Ah * Wl  (reuse aH)
#pragma unroll
            for (int g = 0; g < 2; g++)
                ldm_x4(bL[g], base + 3 * TILE_B + b_lb + (uint32_t)(g * 16 * 80 + s * 32));
#pragma unroll
            for (int mt = 0; mt < 4; mt++)
#pragma unroll
                for (int g = 0; g < 2; g++) {
                    mma_bf16(C[mt][2 * g],     aH[mt], bL[g][0], bL[g][1]);
                    mma_bf16(C[mt][2 * g + 1], aH[mt], bL[g][2], bL[g][3]);
                }
            // combo 3: Al * Wh  (reuse bH; aH dead -> regs recycled)
            uint32_t aL[4][4];
#pragma unroll
            for (int mt = 0; mt < 4; mt++)
                ldm_x4(aL[mt], base + TILE_B + a_lb + (uint32_t)(mt * 16 * 80 + s * 32));
#pragma unroll
            for (int mt = 0; mt < 4; mt++)
#pragma unroll
                for (int g = 0; g < 2; g++) {
                    mma_bf16(C[mt][2 * g],     aL[mt], bH[g][0], bH[g][1]);
                    mma_bf16(C[mt][2 * g + 1], aL[mt], bH[g][2], bH[g][3]);
                }
        }
        __syncthreads();
    }

    // epilogue: direct fp32 stores
    int row0 = bm * 128 + wm * 64 + (lane >> 2);
    int col0 = bn * 128 + wn * 32 + (lane & 3) * 2;
#pragma unroll
    for (int mt = 0; mt < 4; mt++) {
#pragma unroll
        for (int nt = 0; nt < 4; nt++) {
            float* p0 = Cmat + (size_t)(row0 + mt * 16) * Cq + col0 + nt * 8;
            float* p1 = p0 + 8 * Cq;
            *(float2*)p0 = make_float2(C[mt][nt][0], C[mt][nt][1]);
            *(float2*)p1 = make_float2(C[mt][nt][2], C[mt][nt][3]);
        }
    }
}

// ---------------- 3) Phase A: A_c = k^T diag(wk) v per chunk-head -----------
#define PA_SMEM ((Tq * Kq * 2 + Tq) * 4)   // 66048 B

__global__ __launch_bounds__(256)
void phaseA_kernel(const float* __restrict__ kbuf, const float* __restrict__ vbuf,
                   const float* __restrict__ td)
{
    extern __shared__ float sm[];
    float* ks = sm;
    float* vs = ks + Tq * Kq;
    float* pw = vs + Tq * Kq;

    int cb = blockIdx.x;
    int h  = cb % Hq;
    int b  = (cb / Hq) % Bq;
    int c  = cb / (Hq * Bq);
    int t  = threadIdx.x;

    const float* kp = kbuf + ((size_t)(b * TTq + c * Tq)) * Cq + h * Kq;
    const float* vp = vbuf + ((size_t)(b * TTq + c * Tq)) * Cq + h * Kq;
#pragma unroll
    for (int l = 0; l < 8; l++) {
        int lin = t + l * 256;
        int row = lin >> 4;
        int c4  = (lin & 15) * 4;
        *(float4*)&ks[row * Kq + c4] = *(const float4*)(kp + (size_t)row * Cq + c4);
        *(float4*)&vs[row * Kq + c4] = *(const float4*)(vp + (size_t)row * Cq + c4);
    }
    float dec = expf(-expf(td[h]));
    if (t == 0) {
        float p = 1.f;
        for (int i = 0; i < Tq; i++) { pw[i] = p; p *= dec; }
    }
    __syncthreads();

    int tp = t >> 4, tq = t & 15;
    float acc[4][4];
#pragma unroll
    for (int i = 0; i < 4; i++)
#pragma unroll
        for (int j = 0; j < 4; j++) acc[i][j] = 0.f;

#pragma unroll 4
    for (int j = 0; j < Tq; j++) {
        float w  = pw[Tq - 1 - j];
        float4 a  = *(const float4*)&ks[j * Kq + tp * 4];
        float4 bb = *(const float4*)&vs[j * Kq + tq * 4];
        float a0 = a.x * w, a1 = a.y * w, a2 = a.z * w, a3 = a.w * w;
        acc[0][0] += a0 * bb.x; acc[0][1] += a0 * bb.y; acc[0][2] += a0 * bb.z; acc[0][3] += a0 * bb.w;
        acc[1][0] += a1 * bb.x; acc[1][1] += a1 * bb.y; acc[1][2] += a1 * bb.z; acc[1][3] += a1 * bb.w;
        acc[2][0] += a2 * bb.x; acc[2][1] += a2 * bb.y; acc[2][2] += a2 * bb.z; acc[2][3] += a2 * bb.w;
        acc[3][0] += a3 * bb.x; acc[3][1] += a3 * bb.y; acc[3][2] += a3 * bb.z; acc[3][3] += a3 * bb.w;
    }
    float* Ap = g_A + (size_t)cb * (Kq * Kq);
#pragma unroll
    for (int i = 0; i < 4; i++)
        *(float4*)&Ap[(tp * 4 + i) * Kq + tq * 4] =
            make_float4(acc[i][0], acc[i][1], acc[i][2], acc[i][3]);
}

// ---------------- 4) Phase B: sequential state scan per (b,h) ---------------
__global__ __launch_bounds__(256)
void phaseB_kernel(const float* __restrict__ td)
{
    int bh = blockIdx.x;
    int h = bh % Hq;
    int b = bh / Hq;
    int t = threadIdx.x;

    float dec = expf(-expf(td[h]));
    float ws = 1.f;
    for (int i = 0; i < Tq; i++) ws *= dec;

    float S[16];
#pragma unroll
    for (int i = 0; i < 16; i++) S[i] = 0.f;

    for (int c = 0; c < Nq; c++) {
        size_t base = ((size_t)(c * Bq + b) * Hq + h) * (Kq * Kq);
#pragma unroll
        for (int i = 0; i < 16; i++) {
            int e = t + i * 256;
            g_S[base + e] = S[i];
            S[i] = ws * S[i] + g_A[base + e];
        }
    }
}

// ---------------- 5) Phase C: per-chunk output ------------------------------
#define PC_SMEM ((64 * 132 * 2 + Tq * Kq + Kq * Kq + Tq * 129 + Tq) * 4)  // 183296 B

__global__ __launch_bounds__(256)
void phaseC_kernel(const float* __restrict__ rbuf, const float* __restrict__ kbuf,
                   const float* __restrict__ vbuf, const float* __restrict__ td,
                   const float* __restrict__ tf, float* __restrict__ xo)
{
    extern __shared__ float sm[];
    float* rT  = sm;
    float* kT  = rT + 64 * 132;
    float* vs  = kT + 64 * 132;
    float* Ss  = vs + Tq * Kq;
    float* att = Ss + Kq * Kq;
    float* pw  = att + Tq * 129;

    int cb = blockIdx.x;
    int h  = cb % Hq;
    int b  = (cb / Hq) % Bq;
    int c  = cb / (Hq * Bq);
    int t  = threadIdx.x;

    const float* rp = rbuf + ((size_t)(b * TTq + c * Tq)) * Cq + h * Kq;
    const float* kp = kbuf + ((size_t)(b * TTq + c * Tq)) * Cq + h * Kq;
    const float* vp = vbuf + ((size_t)(b * TTq + c * Tq)) * Cq + h * Kq;

#pragma unroll
    for (int l = 0; l < 8; l++) {
        int lin = t + l * 256;
        int row = lin >> 4;
        int c4  = (lin & 15) * 4;
        float4 rv = *(const float4*)(rp + (size_t)row * Cq + c4);
        float4 kv = *(const float4*)(kp + (size_t)row * Cq + c4);
        float4 vv = *(const float4*)(vp + (size_t)row * Cq + c4);
        rT[(c4 + 0) * 132 + row] = rv.x; rT[(c4 + 1) * 132 + row] = rv.y;
        rT[(c4 + 2) * 132 + row] = rv.z; rT[(c4 + 3) * 132 + row] = rv.w;
        kT[(c4 + 0) * 132 + row] = kv.x; kT[(c4 + 1) * 132 + row] = kv.y;
        kT[(c4 + 2) * 132 + row] = kv.z; kT[(c4 + 3) * 132 + row] = kv.w;
        *(float4*)&vs[row * Kq + c4] = vv;
    }
    {
        const float* Sp = g_S + (size_t)cb * (Kq * Kq);
#pragma unroll
        for (int l = 0; l < 4; l++) {
            int lin = t + l * 256;
            *(float4*)&Ss[lin * 4] = *(const float4*)(Sp + lin * 4);
        }
    }
    float dec = expf(-expf(td[h]));
    float u   = tf[h];
    if (t == 0) {
        float p = 1.f;
        for (int i = 0; i < Tq; i++) { pw[i] = p; p *= dec; }
    }
    __syncthreads();

    // att[i][j] = (r_i . k_j) * w_mat[i][j]; only lower-tri (j <= i) is ever read
    {
        int ti = t >> 4, tj = t & 15;
        int i0 = ti * 8, j0 = tj * 8;
        if (tj <= ti) {
            float acc[8][8];
#pragma unroll
            for (int i = 0; i < 8; i++)
#pragma unroll
                for (int j = 0; j < 8; j++) acc[i][j] = 0.f;
#pragma unroll 4
            for (int k = 0; k < Kq; k++) {
                float4 a0 = *(const float4*)&rT[k * 132 + i0];
                float4 a1 = *(const float4*)&rT[k * 132 + i0 + 4];
                float4 b0 = *(const float4*)&kT[k * 132 + j0];
                float4 b1 = *(const float4*)&kT[k * 132 + j0 + 4];
                float a[8] = { a0.x, a0.y, a0.z, a0.w, a1.x, a1.y, a1.z, a1.w };
                float bb[8] = { b0.x, b0.y, b0.z, b0.w, b1.x, b1.y, b1.z, b1.w };
#pragma unroll
                for (int i = 0; i < 8; i++)
#pragma unroll
                    for (int j = 0; j < 8; j++) acc[i][j] += a[i] * bb[j];
            }
#pragma unroll
            for (int i = 0; i < 8; i++)
#pragma unroll
                for (int j = 0; j < 8; j++) {
                    int gi = i0 + i, gj = j0 + j;
                    float w = (gi > gj) ? pw[gi - gj - 1] : ((gi == gj) ? u : 0.f);
                    att[gi * 129 + gj] = acc[i][j] * w;
                }
        }
    }
    __syncthreads();

    {
        int i0 = (t >> 4) * 8;
        int q0 = (t & 15) * 4;
        float acc[8][4];
#pragma unroll
        for (int i = 0; i < 8; i++)
#pragma unroll
            for (int q = 0; q < 4; q++) acc[i][q] = 0.f;

#pragma unroll 4
        for (int k = 0; k < Kq; k++) {
            float4 a0 = *(const float4*)&rT[k * 132 + i0];
            float4 a1 = *(const float4*)&rT[k * 132 + i0 + 4];
            float4 s4 = *(const float4*)&Ss[k * Kq + q0];
            float a[8] = { a0.x, a0.y, a0.z, a0.w, a1.x, a1.y, a1.z, a1.w };
#pragma unroll
            for (int i = 0; i < 8; i++) {
                acc[i][0] += a[i] * s4.x; acc[i][1] += a[i] * s4.y;
                acc[i][2] += a[i] * s4.z; acc[i][3] += a[i] * s4.w;
            }
        }
#pragma unroll
        for (int i = 0; i < 8; i++) {
            float wbi = pw[i0 + i];
            acc[i][0] *= wbi; acc[i][1] *= wbi; acc[i][2] *= wbi; acc[i][3] *= wbi;
        }
        // causal: rows [i0, i0+8) only consume att columns j < i0+8
        int jmax = i0 + 8;
#pragma unroll 2
        for (int j = 0; j < jmax; j++) {
            float4 v4 = *(const float4*)&vs[j * Kq + q0];
#pragma unroll
            for (int i = 0; i < 8; i++) {
                float aij = att[(i0 + i) * 129 + j];
                acc[i][0] += aij * v4.x; acc[i][1] += aij * v4.y;
                acc[i][2] += aij * v4.z; acc[i][3] += aij * v4.w;
            }
        }
        float* op = xo + ((size_t)(b * TTq + c * Tq)) * Cq + h * Kq;
#pragma unroll
        for (int i = 0; i < 8; i++)
            *(float4*)(op + (size_t)(i0 + i) * Cq + q0) =
                make_float4(acc[i][0], acc[i][1], acc[i][2], acc[i][3]);
    }
}

// ---------------- 6) GroupNorm + SiLU gate + bf16 split ---------------------
__global__ __launch_bounds__(256)
void gnorm_gate_kernel(const float* __restrict__ lnw, const float* __restrict__ lnb)
{
    int gwarp = (blockIdx.x * 256 + threadIdx.x) >> 5;
    int lane  = threadIdx.x & 31;
    int h = gwarp & (Hq - 1);
    size_t base = (size_t)gwarp * Kq + lane * 2;

    float2 xo2 = *(const float2*)(g_xo + base);
    float y0 = xo2.x * 0.125f, y1 = xo2.y * 0.125f;
    float s1 = y0 + y1, s2 = y0 * y0 + y1 * y1;
#pragma unroll
    for (int o = 16; o; o >>= 1) {
        s1 += __shfl_xor_sync(0xffffffffu, s1, o);
        s2 += __shfl_xor_sync(0xffffffffu, s2, o);
    }
    float mean = s1 * (1.f / 64.f);
    float var  = s2 * (1.f / 64.f) - mean * mean;
    float rstd = rsqrtf(var + 1e-5f);

    int ci = h * Kq + lane * 2;
    float w0 = lnw[ci], w1 = lnw[ci + 1];
    float b0 = lnb[ci], b1 = lnb[ci + 1];

    float2 g2 = *(const float2*)(g_g + base);
    float sg0 = g2.x / (1.f + expf(-g2.x));
    float sg1 = g2.y / (1.f + expf(-g2.y));

    float o0 = ((y0 - mean) * rstd * w0 + b0) * sg0;
    float o1 = ((y1 - mean) * rstd * w1 + b1) * sg1;

    __nv_bfloat16 h0 = __float2bfloat16(o0), h1 = __float2bfloat16(o1);
    __nv_bfloat16 l0 = __float2bfloat16(o0 - __bfloat162float(h0));
    __nv_bfloat16 l1 = __float2bfloat16(o1 - __bfloat162float(h1));
    __nv_bfloat162 hv; hv.x = h0; hv.y = h1;
    __nv_bfloat162 lv; lv.x = l0; lv.y = l1;
    *(__nv_bfloat162*)(g_yh + base) = hv;
    *(__nv_bfloat162*)(g_yl + base) = lv;
}

// ---------------- launcher ---------------------------------------------------
extern "C" void kernel_launch(void* const* d_in, const int* in_sizes, int n_in,
                              void* d_out, int out_size)
{
    (void)in_sizes; (void)n_in; (void)out_size;
    const float* x   = (const float*)d_in[0];
    const float* tmk = (const float*)d_in[1];
    const float* tmv = (const float*)d_in[2];
    const float* tmr = (const float*)d_in[3];
    const float* tmg = (const float*)d_in[4];
    const float* td  = (const float*)d_in[5];
    const float* tf  = (const float*)d_in[6];
    const float* Wr  = (const float*)d_in[7];
    const float* Wk  = (const float*)d_in[8];
    const float* Wv  = (const float*)d_in[9];
    const float* Wg  = (const float*)d_in[10];
    const float* Wo  = (const float*)d_in[11];
    const float* lnw = (const float*)d_in[12];
    const float* lnb = (const float*)d_in[13];
    float* out = (float*)d_out;

    __nv_bfloat16 *p_xrh, *p_xrl, *p_xkh, *p_xkl, *p_xvh, *p_xvl, *p_xgh, *p_xgl;
    __nv_bfloat16 *p_yh, *p_yl, *p_Wh, *p_Wl;
    float *p_r, *p_k, *p_v, *p_g, *p_xo;
    cudaGetSymbolAddress((void**)&p_xrh, g_xrh);
    cudaGetSymbolAddress((void**)&p_xrl, g_xrl);
    cudaGetSymbolAddress((void**)&p_xkh, g_xkh);
    cudaGetSymbolAddress((void**)&p_xkl, g_xkl);
    cudaGetSymbolAddress((void**)&p_xvh, g_xvh);
    cudaGetSymbolAddress((void**)&p_xvl, g_xvl);
    cudaGetSymbolAddress((void**)&p_xgh, g_xgh);
    cudaGetSymbolAddress((void**)&p_xgl, g_xgl);
    cudaGetSymbolAddress((void**)&p_yh,  g_yh);
    cudaGetSymbolAddress((void**)&p_yl,  g_yl);
    cudaGetSymbolAddress((void**)&p_Wh,  g_Wh);
    cudaGetSymbolAddress((void**)&p_Wl,  g_Wl);
    cudaGetSymbolAddress((void**)&p_r,   g_r);
    cudaGetSymbolAddress((void**)&p_k,   g_k);
    cudaGetSymbolAddress((void**)&p_v,   g_v);
    cudaGetSymbolAddress((void**)&p_g,   g_g);
    cudaGetSymbolAddress((void**)&p_xo,  g_xo);

    cudaFuncSetAttribute(gemm_hmma, cudaFuncAttributeMaxDynamicSharedMemorySize, GSMEM);
    cudaFuncSetAttribute(phaseA_kernel, cudaFuncAttributeMaxDynamicSharedMemorySize, PA_SMEM);
    cudaFuncSetAttribute(phaseC_kernel, cudaFuncAttributeMaxDynamicSharedMemorySize, PC_SMEM);

    mix_split_kernel<<<(BT * Cq) / 4 / 256, 256>>>(x, tmr, tmk, tmv, tmg);

    dim3 wgrid((Cq * Cq) / 4 / 256, 5);
    wsplit5_kernel<<<wgrid, 256>>>(Wr, Wk, Wv, Wg, Wo, p_Wh, p_Wl);

    dim3 ggrid(Cq / 128, BT / 128);   // (8, 128)
    gemm_hmma<<<ggrid, 256, GSMEM>>>(p_xrh, p_xrl, p_Wh + 0 * Cq * Cq, p_Wl + 0 * Cq * Cq, p_r);
    gemm_hmma<<<ggrid, 256, GSMEM>>>(p_xkh, p_xkl, p_Wh + 1 * Cq * Cq, p_Wl + 1 * Cq * Cq, p_k);
    gemm_hmma<<<ggrid, 256, GSMEM>>>(p_xvh, p_xvl, p_Wh + 2 * Cq * Cq, p_Wl + 2 * Cq * Cq, p_v);
    gemm_hmma<<<ggrid, 256, GSMEM>>>(p_xgh, p_xgl, p_Wh + 3 * Cq * Cq, p_Wl + 3 * Cq * Cq, p_g);

    phaseA_kernel<<<Nq * Bq * Hq, 256, PA_SMEM>>>(p_k, p_v, td);
    phaseB_kernel<<<Bq * Hq, 256>>>(td);
    phaseC_kernel<<<Nq * Bq * Hq, 256, PC_SMEM>>>(p_r, p_k, p_v, td, tf, p_xo);

    gnorm_gate_kernel<<<(BT * Hq) / 8, 256>>>(lnw, lnb);

    gemm_hmma<<<ggrid, 256, GSMEM>>>(p_yh, p_yl, p_Wh + 4 * Cq * Cq, p_Wl + 4 * Cq * Cq, out);
}